// round 3
// baseline (speedup 1.0000x reference)
#include <cuda_runtime.h>
#include <cuda_bf16.h>
#include <stdint.h>
#include <stddef.h>

#define Bsz 64
#define Ssz 128
#define Tsz 64
#define Vsz 10000
#define Esz 128
#define Hsz 256

// ---------------- device scratch (no dynamic allocation allowed) ----------------
__device__ float g_emb[Bsz * Ssz * Esz];            // encoder embedded input
__device__ float g_xW[Bsz * Ssz * 2048];            // x@Wih.T+b, both dirs (reused L1/L2)
__device__ float g_out1[Bsz * Ssz * 2 * Hsz];       // layer-1 bilstm out
__device__ float g_enc[Bsz * Ssz * 2 * Hsz];        // layer-2 bilstm out (enc_out)
__device__ float g_encWa[Bsz * Ssz * Hsz];          // enc_out @ Wa[:,H:].T
__device__ float g_T1[Esz * 2048];                  // [k][dir*1024+r] layer1 WihT concat
__device__ float g_T2[2 * Hsz * 2048];              // layer2
__device__ float g_b1c[2048];
__device__ float g_b2c[2048];
__device__ float g_WhhT4[4 * 256 * 1024];           // [layer][dir] k-major 4-interleaved
__device__ float g_Wa1T[256 * 256];                 // [k][h]
__device__ float g_Wa2T[512 * 256];                 // [k][h]
__device__ float g_dWT4[640 * 1024];                // dWih k-major 4-interleaved
__device__ float g_WfcT[768 * Vsz];                 // [k][v]
__device__ float g_h[2][2 * Bsz * Hsz];             // double-buffered h state (dir,b,j)
__device__ float g_c[2 * Bsz * Hsz];                // c state
__device__ float g_hid[Bsz * Hsz];                  // decoder hidden
__device__ float g_hWa[Bsz * Hsz];
__device__ float g_xin[Bsz * 640];                  // [embedded(128), context(512)]
__device__ int   g_tok[Bsz];
__device__ float g_hc[63 * Bsz * 768];              // per-step [h, context]

// ---------------- fast math helpers ----------------
__device__ __forceinline__ float sigf(float x) {
    return __fdividef(1.f, 1.f + __expf(-x));
}
__device__ __forceinline__ float tanf_(float x) {
    x = fminf(fmaxf(x, -15.f), 15.f);
    float e = __expf(2.f * x);
    return __fdividef(e - 1.f, e + 1.f);
}

// ---------------- utility kernels ----------------
__global__ void zeroK(float* p, int n) {
    int i = blockIdx.x * 256 + threadIdx.x;
    if (i < n) p[i] = 0.f;
}

// dst[k*ds + co + r] = src[r*ss + so + k]   (r-fastest index for coalesced writes)
__global__ void tpose(const float* __restrict__ src, float* __restrict__ dst,
                      int R, int Kc, int ss, int so, int ds, int co) {
    int i = blockIdx.x * 256 + threadIdx.x;
    if (i >= R * Kc) return;
    int r = i % R, k = i / R;
    dst[(size_t)k * ds + co + r] = src[(size_t)r * ss + so + k];
}

// dst[(k>>2)*(R*4) + r*4 + (k&3)] = src[r*K + k]
__global__ void tpose4(const float* __restrict__ src, float* __restrict__ dst,
                       int R, int Kc) {
    int i = blockIdx.x * 256 + threadIdx.x;
    if (i >= R * Kc) return;
    int r = i % R, k = i / R;
    dst[(size_t)(k >> 2) * (R * 4) + r * 4 + (k & 3)] = src[(size_t)r * Kc + k];
}

__global__ void biascat(const float* __restrict__ f, const float* __restrict__ b,
                        float* __restrict__ dst) {
    int i = blockIdx.x * 256 + threadIdx.x;
    if (i < 1024) { dst[i] = f[i]; dst[1024 + i] = b[i]; }
}

__global__ void embed_gather(const int* __restrict__ src, const float* __restrict__ emb,
                             float* __restrict__ out) {
    int row = blockIdx.x;                 // b*S+s
    out[(size_t)row * Esz + threadIdx.x] = emb[(size_t)src[row] * Esz + threadIdx.x];
}

// ---------------- generic fp32 GEMM: C[M,N] = A[M,K] @ B[K,N] (+bias) ----------------
// BM=BN=64, BK=16, 256 threads, 4x4 microtile. mode 1: scatter rows into d_out.
__global__ __launch_bounds__(256) void gemm64(
    const float* __restrict__ A, const float* __restrict__ B,
    const float* __restrict__ bias, float* __restrict__ C,
    int M, int N, int K, int mode) {
    __shared__ float As[16][64];
    __shared__ float Bs[16][64];
    int mb = blockIdx.x * 64, nb = blockIdx.y * 64;
    int tid = threadIdx.x;
    int tx = tid & 15, ty = tid >> 4;
    int am = tid >> 2, ak = (tid & 3) * 4;
    int bk = tid >> 4, bc = (tid & 15) * 4;
    float acc[4][4];
#pragma unroll
    for (int i = 0; i < 4; i++)
#pragma unroll
        for (int j = 0; j < 4; j++) acc[i][j] = 0.f;

    const float* Aptr = A + (size_t)(mb + am) * K + ak;
    int colb = nb + bc;
    for (int k0 = 0; k0 < K; k0 += 16) {
        float4 av = *(const float4*)(Aptr + k0);
        As[ak + 0][am] = av.x; As[ak + 1][am] = av.y;
        As[ak + 2][am] = av.z; As[ak + 3][am] = av.w;
        float4 bv;
        if (colb < N) bv = *(const float4*)(B + (size_t)(k0 + bk) * N + colb);
        else bv = make_float4(0.f, 0.f, 0.f, 0.f);
        *(float4*)&Bs[bk][bc] = bv;
        __syncthreads();
#pragma unroll
        for (int kk = 0; kk < 16; kk++) {
            float4 a = *(float4*)&As[kk][ty * 4];
            float4 b = *(float4*)&Bs[kk][tx * 4];
            acc[0][0] += a.x * b.x; acc[0][1] += a.x * b.y; acc[0][2] += a.x * b.z; acc[0][3] += a.x * b.w;
            acc[1][0] += a.y * b.x; acc[1][1] += a.y * b.y; acc[1][2] += a.y * b.z; acc[1][3] += a.y * b.w;
            acc[2][0] += a.z * b.x; acc[2][1] += a.z * b.y; acc[2][2] += a.z * b.z; acc[2][3] += a.z * b.w;
            acc[3][0] += a.w * b.x; acc[3][1] += a.w * b.y; acc[3][2] += a.w * b.z; acc[3][3] += a.w * b.w;
        }
        __syncthreads();
    }
#pragma unroll
    for (int i = 0; i < 4; i++) {
        int r = mb + ty * 4 + i;
        float* crow;
        if (mode == 1) {
            int b = r & 63, st = r >> 6;
            crow = C + ((size_t)b * Tsz + st + 1) * Vsz;     // out[b][st+1][:]
        } else {
            crow = C + (size_t)r * N;
        }
#pragma unroll
        for (int j = 0; j < 4; j++) {
            int col = nb + tx * 4 + j;
            if (col < N) crow[col] = acc[i][j] + (bias ? bias[col] : 0.f);
        }
    }
}

// ---------------- encoder LSTM recurrence step (both directions) ----------------
// grid (4 jchunk, 16 bgroup, 2 dir), 256 threads (4 gates x 64 j), 4 batches/thread
__global__ __launch_bounds__(256) void lstm_step(
    const float* __restrict__ xW, const float* __restrict__ WhhT4,
    const float* __restrict__ hprev, float* __restrict__ hnext,
    float* __restrict__ cstate, float* __restrict__ out, int t) {
    int jc = blockIdx.x, bg = blockIdx.y, d = blockIdx.z;
    int tid = threadIdx.x;
    __shared__ float4 hsm[4][64];        // [bi][k4]
    __shared__ float part[4][4][64];     // [g][bi][j]
    {
        int bi = tid >> 6, k4 = tid & 63;
        hsm[bi][k4] = *(const float4*)(hprev + ((size_t)(d * 64 + bg * 4 + bi)) * Hsz + k4 * 4);
    }
    __syncthreads();
    int g = tid >> 6, j = tid & 63;
    const float* Wp = WhhT4 + (size_t)d * (256 * 1024) + (g * 256 + jc * 64 + j) * 4;
    float a0 = 0.f, a1 = 0.f, a2 = 0.f, a3 = 0.f;
#pragma unroll 4
    for (int k4 = 0; k4 < 64; k4++) {
        float4 w = *(const float4*)(Wp + (size_t)k4 * 4096);
        float4 h0 = hsm[0][k4], h1 = hsm[1][k4], h2 = hsm[2][k4], h3 = hsm[3][k4];
        a0 += w.x * h0.x + w.y * h0.y + w.z * h0.z + w.w * h0.w;
        a1 += w.x * h1.x + w.y * h1.y + w.z * h1.z + w.w * h1.w;
        a2 += w.x * h2.x + w.y * h2.y + w.z * h2.z + w.w * h2.w;
        a3 += w.x * h3.x + w.y * h3.y + w.z * h3.z + w.w * h3.w;
    }
    part[g][0][j] = a0; part[g][1][j] = a1; part[g][2][j] = a2; part[g][3][j] = a3;
    __syncthreads();
    int bi = tid >> 6, j2 = tid & 63;
    int b = bg * 4 + bi, jg = jc * 64 + j2;
    int s = (d == 0) ? t : (Ssz - 1 - t);
    int row = b * Ssz + s;
    const float* xr = xW + (size_t)row * 2048 + d * 1024;
    float gi = part[0][bi][j2] + xr[jg];
    float gf = part[1][bi][j2] + xr[256 + jg];
    float gg = part[2][bi][j2] + xr[512 + jg];
    float go = part[3][bi][j2] + xr[768 + jg];
    int si = (d * 64 + b) * Hsz + jg;
    float c = sigf(gf) * cstate[si] + sigf(gi) * tanf_(gg);
    cstate[si] = c;
    float h = sigf(go) * tanf_(c);
    hnext[si] = h;
    out[(size_t)row * (2 * Hsz) + d * Hsz + jg] = h;
}

// ---------------- decoder kernels ----------------
__global__ void dec_init(const float* __restrict__ enc, const int* __restrict__ trg,
                         float* __restrict__ hid, int* __restrict__ tok) {
    int b = blockIdx.x, tid = threadIdx.x;
    hid[b * Hsz + tid] = enc[((size_t)b * Ssz + (Ssz - 1)) * (2 * Hsz) + tid];
    if (tid == 0) tok[b] = trg[b * Tsz + 0];
}

// hWa = hid @ Wa[:,:H].T + ba ; also gather embedding into xin[0:128]
__global__ void dec_pre(const float* __restrict__ hid, const float* __restrict__ Wa1T,
                        const float* __restrict__ ba, float* __restrict__ hWa,
                        const int* __restrict__ tok, const float* __restrict__ demb,
                        float* __restrict__ xin) {
    int b = blockIdx.x, tid = threadIdx.x;
    __shared__ float hsm[Hsz];
    hsm[tid] = hid[b * Hsz + tid];
    __syncthreads();
    float acc = ba[tid];
#pragma unroll 8
    for (int k = 0; k < Hsz; k++) acc += hsm[k] * Wa1T[k * Hsz + tid];
    hWa[b * Hsz + tid] = acc;
    if (tid < Esz) xin[b * 640 + tid] = demb[(size_t)tok[b] * Esz + tid];
}

// attention: scores -> softmax -> context; writes xin[128:640] and hc[256:768]
__global__ __launch_bounds__(256) void attention(
    const float* __restrict__ hWa, const float* __restrict__ encWa,
    const float* __restrict__ enc, const float* __restrict__ vvec,
    float* __restrict__ xin, float* __restrict__ hc, int st) {
    int b = blockIdx.x, tid = threadIdx.x;
    __shared__ float hs[Hsz], vs[Hsz], sc[Ssz];
    __shared__ float redm, reds;
    hs[tid] = hWa[b * Hsz + tid];
    vs[tid] = vvec[tid];
    __syncthreads();
    int w = tid >> 5, l = tid & 31;
#pragma unroll
    for (int i = 0; i < 16; i++) {
        int s = w * 16 + i;
        const float* ep = encWa + ((size_t)b * Ssz + s) * Hsz;
        float acc = 0.f;
#pragma unroll
        for (int q = 0; q < 8; q++) {
            int h = l + q * 32;
            acc += tanf_(hs[h] + ep[h]) * vs[h];
        }
#pragma unroll
        for (int o = 16; o; o >>= 1) acc += __shfl_xor_sync(0xFFFFFFFFu, acc, o);
        if (l == 0) sc[s] = acc;
    }
    __syncthreads();
    if (tid < 32) {
        float m = fmaxf(fmaxf(sc[tid], sc[tid + 32]), fmaxf(sc[tid + 64], sc[tid + 96]));
#pragma unroll
        for (int o = 16; o; o >>= 1) m = fmaxf(m, __shfl_xor_sync(0xFFFFFFFFu, m, o));
        if (tid == 0) redm = m;
    }
    __syncthreads();
    float mx = redm;
    if (tid < Ssz) sc[tid] = __expf(sc[tid] - mx);
    __syncthreads();
    if (tid < 32) {
        float s_ = sc[tid] + sc[tid + 32] + sc[tid + 64] + sc[tid + 96];
#pragma unroll
        for (int o = 16; o; o >>= 1) s_ += __shfl_xor_sync(0xFFFFFFFFu, s_, o);
        if (tid == 0) reds = __fdividef(1.f, s_);
    }
    __syncthreads();
    float inv = reds;
    float c0 = 0.f, c1 = 0.f;
    const float* eb = enc + (size_t)b * Ssz * (2 * Hsz);
    for (int s = 0; s < Ssz; s++) {
        float a = sc[s] * inv;
        c0 += a * eb[s * 512 + tid];
        c1 += a * eb[s * 512 + 256 + tid];
    }
    xin[b * 640 + 128 + tid] = c0;
    xin[b * 640 + 384 + tid] = c1;
    float* hcb = hc + ((size_t)st * Bsz + b) * 768;
    hcb[256 + tid] = c0;
    hcb[512 + tid] = c1;
}

// decoder gates: g = xin @ dWih.T + db ; h = sig(o)*tanh(sig(i)*tanh(gg))
// grid (4 jchunk, 16 bgroup), 256 threads
__global__ __launch_bounds__(256) void dec_gates(
    const float* __restrict__ xin, const float* __restrict__ dWT4,
    const float* __restrict__ db, float* __restrict__ hid,
    float* __restrict__ hc, int st) {
    int jc = blockIdx.x, bg = blockIdx.y, tid = threadIdx.x;
    __shared__ float4 xs[4][160];
    __shared__ float part[4][4][64];
    for (int i = tid; i < 4 * 160; i += 256) {
        int bi = i / 160, k4 = i % 160;
        xs[bi][k4] = *(const float4*)(xin + (size_t)(bg * 4 + bi) * 640 + k4 * 4);
    }
    __syncthreads();
    int g = tid >> 6, j = tid & 63;
    const float* Wp = dWT4 + (g * 256 + jc * 64 + j) * 4;
    float a0 = 0.f, a1 = 0.f, a2 = 0.f, a3 = 0.f;
#pragma unroll 4
    for (int k4 = 0; k4 < 160; k4++) {
        float4 w = *(const float4*)(Wp + (size_t)k4 * 4096);
        float4 h0 = xs[0][k4], h1 = xs[1][k4], h2 = xs[2][k4], h3 = xs[3][k4];
        a0 += w.x * h0.x + w.y * h0.y + w.z * h0.z + w.w * h0.w;
        a1 += w.x * h1.x + w.y * h1.y + w.z * h1.z + w.w * h1.w;
        a2 += w.x * h2.x + w.y * h2.y + w.z * h2.z + w.w * h2.w;
        a3 += w.x * h3.x + w.y * h3.y + w.z * h3.z + w.w * h3.w;
    }
    part[g][0][j] = a0; part[g][1][j] = a1; part[g][2][j] = a2; part[g][3][j] = a3;
    __syncthreads();
    int bi = tid >> 6, j2 = tid & 63;
    int b = bg * 4 + bi, jg = jc * 64 + j2;
    float gi = part[0][bi][j2] + db[jg];
    float gg = part[2][bi][j2] + db[512 + jg];
    float go = part[3][bi][j2] + db[768 + jg];
    float c = sigf(gi) * tanf_(gg);
    float h = sigf(go) * tanf_(c);
    hid[b * Hsz + jg] = h;
    hc[((size_t)st * Bsz + b) * 768 + jg] = h;
}

// next token: teacher forcing (fast path) or argmax over V (fallback)
__global__ void next_tok(const int* __restrict__ trg, const int* __restrict__ tfmask,
                         int t, const float* __restrict__ hc_step,
                         const float* __restrict__ Wfc, const float* __restrict__ bfc,
                         int* __restrict__ tok) {
    int b = blockIdx.x, tid = threadIdx.x;
    if (tfmask[t] != 0) {
        if (tid == 0) tok[b] = trg[b * Tsz + t];
        return;
    }
    __shared__ float x[768];
    __shared__ float bv[256];
    __shared__ int bidn[256];
    for (int i = tid; i < 768; i += 256) x[i] = hc_step[(size_t)b * 768 + i];
    __syncthreads();
    float best = -1e30f;
    int bidx = 0;
    for (int v0 = tid; v0 < Vsz; v0 += 256) {
        float s = bfc[v0];
        const float* wr = Wfc + (size_t)v0 * 768;
        for (int k = 0; k < 768; k++) s += x[k] * wr[k];
        if (s > best) { best = s; bidx = v0; }
    }
    bv[tid] = best; bidn[tid] = bidx;
    __syncthreads();
    for (int off = 128; off; off >>= 1) {
        if (tid < off) {
            if (bv[tid + off] > bv[tid] ||
                (bv[tid + off] == bv[tid] && bidn[tid + off] < bidn[tid])) {
                bv[tid] = bv[tid + off];
                bidn[tid] = bidn[tid + off];
            }
        }
        __syncthreads();
    }
    if (tid == 0) tok[b] = bidn[0];
}

__global__ void zero_t0(float* __restrict__ out) {
    int b = blockIdx.x;
    int v = blockIdx.y * 256 + threadIdx.x;
    if (v < Vsz) out[(size_t)b * Tsz * Vsz + v] = 0.f;
}

// ---------------- host launch ----------------
static float* symaddr(const void* sym) {
    void* p = nullptr;
    cudaGetSymbolAddress(&p, sym);
    return (float*)p;
}

extern "C" void kernel_launch(void* const* d_in, const int* in_sizes, int n_in,
                              void* d_out, int out_size) {
    const int*   src     = (const int*)d_in[0];
    const int*   trg     = (const int*)d_in[1];
    const int*   tfmask  = (const int*)d_in[2];
    const float* enc_emb = (const float*)d_in[3];
    const float* e1f_Wih = (const float*)d_in[4];
    const float* e1f_Whh = (const float*)d_in[5];
    const float* e1f_b   = (const float*)d_in[6];
    const float* e1b_Wih = (const float*)d_in[7];
    const float* e1b_Whh = (const float*)d_in[8];
    const float* e1b_b   = (const float*)d_in[9];
    const float* e2f_Wih = (const float*)d_in[10];
    const float* e2f_Whh = (const float*)d_in[11];
    const float* e2f_b   = (const float*)d_in[12];
    const float* e2b_Wih = (const float*)d_in[13];
    const float* e2b_Whh = (const float*)d_in[14];
    const float* e2b_b   = (const float*)d_in[15];
    const float* dec_emb = (const float*)d_in[16];
    const float* Wa      = (const float*)d_in[17];
    const float* ba      = (const float*)d_in[18];
    const float* vvec    = (const float*)d_in[19];
    const float* dWih    = (const float*)d_in[20];
    const float* db      = (const float*)d_in[21];
    const float* Wfc     = (const float*)d_in[22];
    const float* bfc     = (const float*)d_in[23];
    float* out = (float*)d_out;

    float* p_emb   = symaddr(g_emb);
    float* p_xW    = symaddr(g_xW);
    float* p_out1  = symaddr(g_out1);
    float* p_enc   = symaddr(g_enc);
    float* p_encWa = symaddr(g_encWa);
    float* p_T1    = symaddr(g_T1);
    float* p_T2    = symaddr(g_T2);
    float* p_b1c   = symaddr(g_b1c);
    float* p_b2c   = symaddr(g_b2c);
    float* p_WhhT4 = symaddr(g_WhhT4);
    float* p_Wa1T  = symaddr(g_Wa1T);
    float* p_Wa2T  = symaddr(g_Wa2T);
    float* p_dWT4  = symaddr(g_dWT4);
    float* p_WfcT  = symaddr(g_WfcT);
    float* p_h0    = symaddr(g_h);                  // g_h[0]
    float* p_h1    = p_h0 + 2 * Bsz * Hsz;          // g_h[1]
    float* p_c     = symaddr(g_c);
    float* p_hid   = symaddr(g_hid);
    float* p_hWa   = symaddr(g_hWa);
    float* p_xin   = symaddr(g_xin);
    int*   p_tok   = (int*)symaddr(g_tok);
    float* p_hc    = symaddr(g_hc);

    // ---- weight prep (transposes / concat) ----
    auto nb = [](int n) { return (n + 255) / 256; };
    tpose<<<nb(1024 * 128), 256>>>(e1f_Wih, p_T1, 1024, 128, 128, 0, 2048, 0);
    tpose<<<nb(1024 * 128), 256>>>(e1b_Wih, p_T1, 1024, 128, 128, 0, 2048, 1024);
    tpose<<<nb(1024 * 512), 256>>>(e2f_Wih, p_T2, 1024, 512, 512, 0, 2048, 0);
    tpose<<<nb(1024 * 512), 256>>>(e2b_Wih, p_T2, 1024, 512, 512, 0, 2048, 1024);
    tpose<<<nb(256 * 256), 256>>>(Wa, p_Wa1T, 256, 256, 768, 0, 256, 0);
    tpose<<<nb(256 * 512), 256>>>(Wa, p_Wa2T, 256, 512, 768, 256, 256, 0);
    tpose<<<nb(Vsz * 768), 256>>>(Wfc, p_WfcT, Vsz, 768, 768, 0, Vsz, 0);
    tpose4<<<nb(1024 * 256), 256>>>(e1f_Whh, p_WhhT4 + 0 * 262144, 1024, 256);
    tpose4<<<nb(1024 * 256), 256>>>(e1b_Whh, p_WhhT4 + 1 * 262144, 1024, 256);
    tpose4<<<nb(1024 * 256), 256>>>(e2f_Whh, p_WhhT4 + 2 * 262144, 1024, 256);
    tpose4<<<nb(1024 * 256), 256>>>(e2b_Whh, p_WhhT4 + 3 * 262144, 1024, 256);
    tpose4<<<nb(1024 * 640), 256>>>(dWih, p_dWT4, 1024, 640);
    biascat<<<4, 256>>>(e1f_b, e1b_b, p_b1c);
    biascat<<<4, 256>>>(e2f_b, e2b_b, p_b2c);

    // ---- encoder ----
    embed_gather<<<Bsz * Ssz, Esz>>>(src, enc_emb, p_emb);
    gemm64<<<dim3(Bsz * Ssz / 64, 2048 / 64), 256>>>(p_emb, p_T1, p_b1c, p_xW,
                                                     Bsz * Ssz, 2048, 128, 0);
    zeroK<<<nb(2 * Bsz * Hsz), 256>>>(p_h0, 2 * Bsz * Hsz);
    zeroK<<<nb(2 * Bsz * Hsz), 256>>>(p_c, 2 * Bsz * Hsz);
    for (int t = 0; t < Ssz; t++) {
        float* hp = (t & 1) ? p_h1 : p_h0;
        float* hn = (t & 1) ? p_h0 : p_h1;
        lstm_step<<<dim3(4, 16, 2), 256>>>(p_xW, p_WhhT4, hp, hn, p_c, p_out1, t);
    }
    gemm64<<<dim3(Bsz * Ssz / 64, 2048 / 64), 256>>>(p_out1, p_T2, p_b2c, p_xW,
                                                     Bsz * Ssz, 2048, 512, 0);
    zeroK<<<nb(2 * Bsz * Hsz), 256>>>(p_h0, 2 * Bsz * Hsz);
    zeroK<<<nb(2 * Bsz * Hsz), 256>>>(p_c, 2 * Bsz * Hsz);
    for (int t = 0; t < Ssz; t++) {
        float* hp = (t & 1) ? p_h1 : p_h0;
        float* hn = (t & 1) ? p_h0 : p_h1;
        lstm_step<<<dim3(4, 16, 2), 256>>>(p_xW, p_WhhT4 + 2 * 262144, hp, hn, p_c, p_enc, t);
    }

    // ---- attention precompute + decoder ----
    gemm64<<<dim3(Bsz * Ssz / 64, 256 / 64), 256>>>(p_enc, p_Wa2T, nullptr, p_encWa,
                                                    Bsz * Ssz, 256, 512, 0);
    dec_init<<<Bsz, Hsz>>>(p_enc, trg, p_hid, p_tok);
    for (int st = 0; st < Tsz - 1; st++) {
        dec_pre<<<Bsz, Hsz>>>(p_hid, p_Wa1T, ba, p_hWa, p_tok, dec_emb, p_xin);
        attention<<<Bsz, 256>>>(p_hWa, p_encWa, p_enc, vvec, p_xin, p_hc, st);
        dec_gates<<<dim3(4, 16), 256>>>(p_xin, p_dWT4, db, p_hid, p_hc, st);
        if (st < Tsz - 2) {
            next_tok<<<Bsz, 256>>>(trg, tfmask, st + 1,
                                   p_hc + (size_t)st * Bsz * 768, Wfc, bfc, p_tok);
        }
    }

    // ---- final projection: [h,context] @ Wfc.T + bfc, scattered into out ----
    gemm64<<<dim3((Tsz - 1) * Bsz / 64, (Vsz + 63) / 64), 256>>>(
        p_hc, p_WfcT, bfc, out, (Tsz - 1) * Bsz, Vsz, 768, 1);
    zero_t0<<<dim3(Bsz, (Vsz + 255) / 256), 256>>>(out);
}

// round 5
// speedup vs baseline: 1.2300x; 1.2300x over previous
#include <cuda_runtime.h>
#include <cuda_bf16.h>
#include <stdint.h>
#include <stddef.h>

#define Bsz 64
#define Ssz 128
#define Tsz 64
#define Vsz 10000
#define Esz 128
#define Hsz 256
#define VPAD 10112            // V padded to multiple of 128

// ---------------- device scratch (no dynamic allocation allowed) ----------------
__device__ float g_emb[Bsz * Ssz * Esz];
__device__ float g_xW[Bsz * Ssz * 2048];
__device__ float g_out1[Bsz * Ssz * 2 * Hsz];
__device__ float g_enc[Bsz * Ssz * 2 * Hsz];
__device__ float g_encWa[Bsz * Ssz * Hsz];
__device__ float g_b1c[2048];
__device__ float g_b2c[2048];
__device__ float g_WhhT4[4 * 256 * 1024];
__device__ float g_Wa1T[256 * 256];
__device__ float g_dWT4[640 * 1024];
__device__ float g_h[2][2 * Bsz * Hsz];
__device__ float g_c[2 * Bsz * Hsz];
__device__ float g_hid[Bsz * Hsz];
__device__ float g_hWa[Bsz * Hsz];
__device__ float g_xin[Bsz * 640];
__device__ int   g_tok[Bsz];
__device__ float g_hc[63 * Bsz * 768];

// bf16 split buffers
__device__ __nv_bfloat16 g_Ahi[8192 * 512];
__device__ __nv_bfloat16 g_Alo[8192 * 512];
__device__ __nv_bfloat16 g_B1hi[2048 * 128], g_B1lo[2048 * 128];
__device__ __nv_bfloat16 g_B2hi[2048 * 512], g_B2lo[2048 * 512];
__device__ __nv_bfloat16 g_BWahi[256 * 512], g_BWalo[256 * 512];
__device__ __nv_bfloat16 g_Bfchi[VPAD * 768], g_Bfclo[VPAD * 768];

// ---------------- fast math helpers ----------------
__device__ __forceinline__ float sigf(float x) {
    return __fdividef(1.f, 1.f + __expf(-x));
}
__device__ __forceinline__ float tanf_(float x) {
    x = fminf(fmaxf(x, -15.f), 15.f);
    float e = __expf(2.f * x);
    return __fdividef(e - 1.f, e + 1.f);
}

// ---------------- warp-level bf16 MMA (baseline PTX, works on sm_103) ----------------
__device__ __forceinline__ void mma16816(float* c, const uint32_t* a, const uint32_t* b) {
    asm volatile(
        "mma.sync.aligned.m16n8k16.row.col.f32.bf16.bf16.f32 "
        "{%0,%1,%2,%3}, {%4,%5,%6,%7}, {%8,%9}, {%0,%1,%2,%3};"
        : "+f"(c[0]), "+f"(c[1]), "+f"(c[2]), "+f"(c[3])
        : "r"(a[0]), "r"(a[1]), "r"(a[2]), "r"(a[3]), "r"(b[0]), "r"(b[1]));
}

#define LDSW 72                       // smem row stride (64 data + 8 pad) in bf16
#define TILE_E (128 * LDSW)           // elems per tile buffer
#define TCSM (4 * TILE_E * 2)         // 73728 bytes

// ---------------- bf16 split-precision tensor-core GEMM ----------------
// C[M,N] = (Ahi+Alo)[M,K] @ (Bhi+Blo)[N,K]^T + bias   (3 accumulating terms)
// 128x128 tile, 256 threads (8 warps, 32x64 each), K chunked by 64.
// A/B arrays must be padded: rows M/N up to multiples of 128, zero-filled.
// mode 1: scatter row r -> C[(r&63)*Tsz + (r>>6)+1][*] with row stride Nreal.
__global__ __launch_bounds__(256) void gemm_tc(
    const __nv_bfloat16* __restrict__ Ahi, const __nv_bfloat16* __restrict__ Alo,
    const __nv_bfloat16* __restrict__ Bhi, const __nv_bfloat16* __restrict__ Blo,
    const float* __restrict__ bias, float* __restrict__ C,
    int Mreal, int Nreal, int K, int mode)
{
    extern __shared__ __nv_bfloat16 sm[];
    __nv_bfloat16* sAh = sm;
    __nv_bfloat16* sAl = sm + TILE_E;
    __nv_bfloat16* sBh = sm + 2 * TILE_E;
    __nv_bfloat16* sBl = sm + 3 * TILE_E;

    int tid = threadIdx.x;
    int warp = tid >> 5, lane = tid & 31;
    int m0 = blockIdx.x * 128, n0 = blockIdx.y * 128;
    int mw = (warp >> 1) * 32, nw = (warp & 1) * 64;

    float acc[2][8][4];
#pragma unroll
    for (int i = 0; i < 2; i++)
#pragma unroll
        for (int j = 0; j < 8; j++)
#pragma unroll
            for (int q = 0; q < 4; q++) acc[i][j][q] = 0.f;

    int ar = lane >> 2;                 // fragment row within 8-row group
    int acq = (lane & 3) * 2;           // fragment col pair

    for (int kc = 0; kc < K; kc += 64) {
        // ---- load 4 tiles (A hi/lo rows m0.., B hi/lo rows n0..) ----
#pragma unroll
        for (int i = 0; i < 4; i++) {
            int idx = i * 256 + tid;
            int row = idx >> 3, c8 = (idx & 7) * 8;
            size_t ga = (size_t)(m0 + row) * K + kc + c8;
            size_t gb = (size_t)(n0 + row) * K + kc + c8;
            int so = row * LDSW + c8;
            *(uint4*)&sAh[so] = *(const uint4*)&Ahi[ga];
            *(uint4*)&sAl[so] = *(const uint4*)&Alo[ga];
            *(uint4*)&sBh[so] = *(const uint4*)&Bhi[gb];
            *(uint4*)&sBl[so] = *(const uint4*)&Blo[gb];
        }
        __syncthreads();

#pragma unroll
        for (int term = 0; term < 3; term++) {
            const __nv_bfloat16* As = (term == 2) ? sAl : sAh;
            const __nv_bfloat16* Bs = (term == 1) ? sBl : sBh;
#pragma unroll
            for (int k16 = 0; k16 < 4; k16++) {
                int kb = k16 * 16 + acq;
                uint32_t afr[2][4], bfr[8][2];
#pragma unroll
                for (int mt = 0; mt < 2; mt++) {
                    int base = (mw + mt * 16 + ar) * LDSW + kb;
                    afr[mt][0] = *(const uint32_t*)(As + base);
                    afr[mt][1] = *(const uint32_t*)(As + base + 8 * LDSW);
                    afr[mt][2] = *(const uint32_t*)(As + base + 8);
                    afr[mt][3] = *(const uint32_t*)(As + base + 8 * LDSW + 8);
                }
#pragma unroll
                for (int nt = 0; nt < 8; nt++) {
                    int base = (nw + nt * 8 + ar) * LDSW + kb;
                    bfr[nt][0] = *(const uint32_t*)(Bs + base);
                    bfr[nt][1] = *(const uint32_t*)(Bs + base + 8);
                }
#pragma unroll
                for (int mt = 0; mt < 2; mt++)
#pragma unroll
                    for (int nt = 0; nt < 8; nt++)
                        mma16816(acc[mt][nt], afr[mt], bfr[nt]);
            }
        }
        __syncthreads();
    }

    // ---- epilogue: bias + store (optional scatter) ----
#pragma unroll
    for (int mt = 0; mt < 2; mt++) {
#pragma unroll
        for (int half = 0; half < 2; half++) {
            int m = m0 + mw + mt * 16 + ar + half * 8;
            if (m >= Mreal) continue;
            float* crow;
            if (mode == 1) {
                int b = m & 63, st = m >> 6;
                crow = C + ((size_t)b * Tsz + st + 1) * (size_t)Nreal;
            } else {
                crow = C + (size_t)m * Nreal;
            }
#pragma unroll
            for (int nt = 0; nt < 8; nt++) {
                int col = n0 + nw + nt * 8 + acq;
                float v0 = acc[mt][nt][half * 2 + 0];
                float v1 = acc[mt][nt][half * 2 + 1];
                if (col < Nreal)     crow[col]     = v0 + (bias ? bias[col] : 0.f);
                if (col + 1 < Nreal) crow[col + 1] = v1 + (bias ? bias[col + 1] : 0.f);
            }
        }
    }
}

// ---------------- fp32 -> bf16 hi/lo split (with row pad + concat offset) ----------------
__global__ void splitbf16(const float* __restrict__ src, __nv_bfloat16* __restrict__ hi,
                          __nv_bfloat16* __restrict__ lo, int rows, int cols, int ld,
                          int coloff, int prows, int rowoff) {
    int i = blockIdx.x * 256 + threadIdx.x;
    if (i >= prows * cols) return;
    int r = i / cols, c = i % cols;
    float x = (r < rows) ? src[(size_t)r * ld + coloff + c] : 0.f;
    __nv_bfloat16 h = __float2bfloat16(x);
    float rem = x - __bfloat162float(h);
    size_t di = (size_t)(r + rowoff) * cols + c;
    hi[di] = h;
    lo[di] = __float2bfloat16(rem);
}

// ---------------- utility kernels ----------------
__global__ void zeroK(float* p, int n) {
    int i = blockIdx.x * 256 + threadIdx.x;
    if (i < n) p[i] = 0.f;
}

__global__ void tpose(const float* __restrict__ src, float* __restrict__ dst,
                      int R, int Kc, int ss, int so, int ds, int co) {
    int i = blockIdx.x * 256 + threadIdx.x;
    if (i >= R * Kc) return;
    int r = i % R, k = i / R;
    dst[(size_t)k * ds + co + r] = src[(size_t)r * ss + so + k];
}

__global__ void tpose4(const float* __restrict__ src, float* __restrict__ dst,
                       int R, int Kc) {
    int i = blockIdx.x * 256 + threadIdx.x;
    if (i >= R * Kc) return;
    int r = i % R, k = i / R;
    dst[(size_t)(k >> 2) * (R * 4) + r * 4 + (k & 3)] = src[(size_t)r * Kc + k];
}

__global__ void biascat(const float* __restrict__ f, const float* __restrict__ b,
                        float* __restrict__ dst) {
    int i = blockIdx.x * 256 + threadIdx.x;
    if (i < 1024) { dst[i] = f[i]; dst[1024 + i] = b[i]; }
}

__global__ void embed_gather(const int* __restrict__ src, const float* __restrict__ emb,
                             float* __restrict__ out) {
    int row = blockIdx.x;
    out[(size_t)row * Esz + threadIdx.x] = emb[(size_t)src[row] * Esz + threadIdx.x];
}

// ---------------- encoder LSTM recurrence step (both directions) ----------------
__global__ __launch_bounds__(256) void lstm_step(
    const float* __restrict__ xW, const float* __restrict__ WhhT4,
    const float* __restrict__ hprev, float* __restrict__ hnext,
    float* __restrict__ cstate, float* __restrict__ out, int t) {
    int jc = blockIdx.x, bg = blockIdx.y, d = blockIdx.z;
    int tid = threadIdx.x;
    __shared__ float4 hsm[4][64];
    __shared__ float part[4][4][64];
    {
        int bi = tid >> 6, k4 = tid & 63;
        hsm[bi][k4] = *(const float4*)(hprev + ((size_t)(d * 64 + bg * 4 + bi)) * Hsz + k4 * 4);
    }
    __syncthreads();
    int g = tid >> 6, j = tid & 63;
    const float* Wp = WhhT4 + (size_t)d * (256 * 1024) + (g * 256 + jc * 64 + j) * 4;
    float a0 = 0.f, a1 = 0.f, a2 = 0.f, a3 = 0.f;
#pragma unroll 4
    for (int k4 = 0; k4 < 64; k4++) {
        float4 w = *(const float4*)(Wp + (size_t)k4 * 4096);
        float4 h0 = hsm[0][k4], h1 = hsm[1][k4], h2 = hsm[2][k4], h3 = hsm[3][k4];
        a0 += w.x * h0.x + w.y * h0.y + w.z * h0.z + w.w * h0.w;
        a1 += w.x * h1.x + w.y * h1.y + w.z * h1.z + w.w * h1.w;
        a2 += w.x * h2.x + w.y * h2.y + w.z * h2.z + w.w * h2.w;
        a3 += w.x * h3.x + w.y * h3.y + w.z * h3.z + w.w * h3.w;
    }
    part[g][0][j] = a0; part[g][1][j] = a1; part[g][2][j] = a2; part[g][3][j] = a3;
    __syncthreads();
    int bi = tid >> 6, j2 = tid & 63;
    int b = bg * 4 + bi, jg = jc * 64 + j2;
    int s = (d == 0) ? t : (Ssz - 1 - t);
    int row = b * Ssz + s;
    const float* xr = xW + (size_t)row * 2048 + d * 1024;
    float gi = part[0][bi][j2] + xr[jg];
    float gf = part[1][bi][j2] + xr[256 + jg];
    float gg = part[2][bi][j2] + xr[512 + jg];
    float go = part[3][bi][j2] + xr[768 + jg];
    int si = (d * 64 + b) * Hsz + jg;
    float c = sigf(gf) * cstate[si] + sigf(gi) * tanf_(gg);
    cstate[si] = c;
    float h = sigf(go) * tanf_(c);
    hnext[si] = h;
    out[(size_t)row * (2 * Hsz) + d * Hsz + jg] = h;
}

// ---------------- decoder kernels ----------------
__global__ void dec_init(const float* __restrict__ enc, const int* __restrict__ trg,
                         float* __restrict__ hid, int* __restrict__ tok) {
    int b = blockIdx.x, tid = threadIdx.x;
    hid[b * Hsz + tid] = enc[((size_t)b * Ssz + (Ssz - 1)) * (2 * Hsz) + tid];
    if (tid == 0) tok[b] = trg[b * Tsz + 0];
}

__global__ void dec_pre(const float* __restrict__ hid, const float* __restrict__ Wa1T,
                        const float* __restrict__ ba, float* __restrict__ hWa,
                        const int* __restrict__ tok, const float* __restrict__ demb,
                        float* __restrict__ xin) {
    int b = blockIdx.x, tid = threadIdx.x;
    __shared__ float hsm[Hsz];
    hsm[tid] = hid[b * Hsz + tid];
    __syncthreads();
    float acc = ba[tid];
#pragma unroll 8
    for (int k = 0; k < Hsz; k++) acc += hsm[k] * Wa1T[k * Hsz + tid];
    hWa[b * Hsz + tid] = acc;
    if (tid < Esz) xin[b * 640 + tid] = demb[(size_t)tok[b] * Esz + tid];
}

__global__ __launch_bounds__(256) void attention(
    const float* __restrict__ hWa, const float* __restrict__ encWa,
    const float* __restrict__ enc, const float* __restrict__ vvec,
    float* __restrict__ xin, float* __restrict__ hc, int st) {
    int b = blockIdx.x, tid = threadIdx.x;
    __shared__ float hs[Hsz], vs[Hsz], sc[Ssz];
    __shared__ float redm, reds;
    hs[tid] = hWa[b * Hsz + tid];
    vs[tid] = vvec[tid];
    __syncthreads();
    int w = tid >> 5, l = tid & 31;
#pragma unroll
    for (int i = 0; i < 16; i++) {
        int s = w * 16 + i;
        const float* ep = encWa + ((size_t)b * Ssz + s) * Hsz;
        float acc = 0.f;
#pragma unroll
        for (int q = 0; q < 8; q++) {
            int h = l + q * 32;
            acc += tanf_(hs[h] + ep[h]) * vs[h];
        }
#pragma unroll
        for (int o = 16; o; o >>= 1) acc += __shfl_xor_sync(0xFFFFFFFFu, acc, o);
        if (l == 0) sc[s] = acc;
    }
    __syncthreads();
    if (tid < 32) {
        float m = fmaxf(fmaxf(sc[tid], sc[tid + 32]), fmaxf(sc[tid + 64], sc[tid + 96]));
#pragma unroll
        for (int o = 16; o; o >>= 1) m = fmaxf(m, __shfl_xor_sync(0xFFFFFFFFu, m, o));
        if (tid == 0) redm = m;
    }
    __syncthreads();
    float mx = redm;
    if (tid < Ssz) sc[tid] = __expf(sc[tid] - mx);
    __syncthreads();
    if (tid < 32) {
        float s_ = sc[tid] + sc[tid + 32] + sc[tid + 64] + sc[tid + 96];
#pragma unroll
        for (int o = 16; o; o >>= 1) s_ += __shfl_xor_sync(0xFFFFFFFFu, s_, o);
        if (tid == 0) reds = __fdividef(1.f, s_);
    }
    __syncthreads();
    float inv = reds;
    float c0 = 0.f, c1 = 0.f;
    const float* eb = enc + (size_t)b * Ssz * (2 * Hsz);
    for (int s = 0; s < Ssz; s++) {
        float a = sc[s] * inv;
        c0 += a * eb[s * 512 + tid];
        c1 += a * eb[s * 512 + 256 + tid];
    }
    xin[b * 640 + 128 + tid] = c0;
    xin[b * 640 + 384 + tid] = c1;
    float* hcb = hc + ((size_t)st * Bsz + b) * 768;
    hcb[256 + tid] = c0;
    hcb[512 + tid] = c1;
}

__global__ __launch_bounds__(256) void dec_gates(
    const float* __restrict__ xin, const float* __restrict__ dWT4,
    const float* __restrict__ db, float* __restrict__ hid,
    float* __restrict__ hc, int st) {
    int jc = blockIdx.x, bg = blockIdx.y, tid = threadIdx.x;
    __shared__ float4 xs[4][160];
    __shared__ float part[4][4][64];
    for (int i = tid; i < 4 * 160; i += 256) {
        int bi = i / 160, k4 = i % 160;
        xs[bi][k4] = *(const float4*)(xin + (size_t)(bg * 4 + bi) * 640 + k4 * 4);
    }
    __syncthreads();
    int g = tid >> 6, j = tid & 63;
    const float* Wp = dWT4 + (g * 256 + jc * 64 + j) * 4;
    float a0 = 0.f, a1 = 0.f, a2 = 0.f, a3 = 0.f;
#pragma unroll 4
    for (int k4 = 0; k4 < 160; k4++) {
        float4 w = *(const float4*)(Wp + (size_t)k4 * 4096);
        float4 h0 = xs[0][k4], h1 = xs[1][k4], h2 = xs[2][k4], h3 = xs[3][k4];
        a0 += w.x * h0.x + w.y * h0.y + w.z * h0.z + w.w * h0.w;
        a1 += w.x * h1.x + w.y * h1.y + w.z * h1.z + w.w * h1.w;
        a2 += w.x * h2.x + w.y * h2.y + w.z * h2.z + w.w * h2.w;
        a3 += w.x * h3.x + w.y * h3.y + w.z * h3.z + w.w * h3.w;
    }
    part[g][0][j] = a0; part[g][1][j] = a1; part[g][2][j] = a2; part[g][3][j] = a3;
    __syncthreads();
    int bi = tid >> 6, j2 = tid & 63;
    int b = bg * 4 + bi, jg = jc * 64 + j2;
    float gi = part[0][bi][j2] + db[jg];
    float gg = part[2][bi][j2] + db[512 + jg];
    float go = part[3][bi][j2] + db[768 + jg];
    float c = sigf(gi) * tanf_(gg);
    float h = sigf(go) * tanf_(c);
    hid[b * Hsz + jg] = h;
    hc[((size_t)st * Bsz + b) * 768 + jg] = h;
}

__global__ void next_tok(const int* __restrict__ trg, const int* __restrict__ tfmask,
                         int t, const float* __restrict__ hc_step,
                         const float* __restrict__ Wfc, const float* __restrict__ bfc,
                         int* __restrict__ tok) {
    int b = blockIdx.x, tid = threadIdx.x;
    if (tfmask[t] != 0) {
        if (tid == 0) tok[b] = trg[b * Tsz + t];
        return;
    }
    __shared__ float x[768];
    __shared__ float bv[256];
    __shared__ int bidn[256];
    for (int i = tid; i < 768; i += 256) x[i] = hc_step[(size_t)b * 768 + i];
    __syncthreads();
    float best = -1e30f;
    int bidx = 0;
    for (int v0 = tid; v0 < Vsz; v0 += 256) {
        float s = bfc[v0];
        const float* wr = Wfc + (size_t)v0 * 768;
        for (int k = 0; k < 768; k++) s += x[k] * wr[k];
        if (s > best) { best = s; bidx = v0; }
    }
    bv[tid] = best; bidn[tid] = bidx;
    __syncthreads();
    for (int off = 128; off; off >>= 1) {
        if (tid < off) {
            if (bv[tid + off] > bv[tid] ||
                (bv[tid + off] == bv[tid] && bidn[tid + off] < bidn[tid])) {
                bv[tid] = bv[tid + off];
                bidn[tid] = bidn[tid + off];
            }
        }
        __syncthreads();
    }
    if (tid == 0) tok[b] = bidn[0];
}

__global__ void zero_t0(float* __restrict__ out) {
    int b = blockIdx.x;
    int v = blockIdx.y * 256 + threadIdx.x;
    if (v < Vsz) out[(size_t)b * Tsz * Vsz + v] = 0.f;
}

// ---------------- host launch ----------------
static float* symaddr(const void* sym) {
    void* p = nullptr;
    cudaGetSymbolAddress(&p, sym);
    return (float*)p;
}
static __nv_bfloat16* symaddrb(const void* sym) {
    void* p = nullptr;
    cudaGetSymbolAddress(&p, sym);
    return (__nv_bfloat16*)p;
}

extern "C" void kernel_launch(void* const* d_in, const int* in_sizes, int n_in,
                              void* d_out, int out_size) {
    const int*   src     = (const int*)d_in[0];
    const int*   trg     = (const int*)d_in[1];
    const int*   tfmask  = (const int*)d_in[2];
    const float* enc_emb = (const float*)d_in[3];
    const float* e1f_Wih = (const float*)d_in[4];
    const float* e1f_Whh = (const float*)d_in[5];
    const float* e1f_b   = (const float*)d_in[6];
    const float* e1b_Wih = (const float*)d_in[7];
    const float* e1b_Whh = (const float*)d_in[8];
    const float* e1b_b   = (const float*)d_in[9];
    const float* e2f_Wih = (const float*)d_in[10];
    const float* e2f_Whh = (const float*)d_in[11];
    const float* e2f_b   = (const float*)d_in[12];
    const float* e2b_Wih = (const float*)d_in[13];
    const float* e2b_Whh = (const float*)d_in[14];
    const float* e2b_b   = (const float*)d_in[15];
    const float* dec_emb = (const float*)d_in[16];
    const float* Wa      = (const float*)d_in[17];
    const float* ba      = (const float*)d_in[18];
    const float* vvec    = (const float*)d_in[19];
    const float* dWih    = (const float*)d_in[20];
    const float* db      = (const float*)d_in[21];
    const float* Wfc     = (const float*)d_in[22];
    const float* bfc     = (const float*)d_in[23];
    float* out = (float*)d_out;

    float* p_emb   = symaddr(g_emb);
    float* p_xW    = symaddr(g_xW);
    float* p_out1  = symaddr(g_out1);
    float* p_enc   = symaddr(g_enc);
    float* p_encWa = symaddr(g_encWa);
    float* p_b1c   = symaddr(g_b1c);
    float* p_b2c   = symaddr(g_b2c);
    float* p_WhhT4 = symaddr(g_WhhT4);
    float* p_Wa1T  = symaddr(g_Wa1T);
    float* p_dWT4  = symaddr(g_dWT4);
    float* p_h0    = symaddr(g_h);
    float* p_h1    = p_h0 + 2 * Bsz * Hsz;
    float* p_c     = symaddr(g_c);
    float* p_hid   = symaddr(g_hid);
    float* p_hWa   = symaddr(g_hWa);
    float* p_xin   = symaddr(g_xin);
    int*   p_tok   = (int*)symaddr(g_tok);
    float* p_hc    = symaddr(g_hc);

    __nv_bfloat16* p_Ahi = symaddrb(g_Ahi);
    __nv_bfloat16* p_Alo = symaddrb(g_Alo);
    __nv_bfloat16* p_B1hi = symaddrb(g_B1hi), * p_B1lo = symaddrb(g_B1lo);
    __nv_bfloat16* p_B2hi = symaddrb(g_B2hi), * p_B2lo = symaddrb(g_B2lo);
    __nv_bfloat16* p_BWahi = symaddrb(g_BWahi), * p_BWalo = symaddrb(g_BWalo);
    __nv_bfloat16* p_Bfchi = symaddrb(g_Bfchi), * p_Bfclo = symaddrb(g_Bfclo);

    cudaFuncSetAttribute(gemm_tc, cudaFuncAttributeMaxDynamicSharedMemorySize, TCSM);

    auto nb = [](int n) { return (n + 255) / 256; };

    // ---- weight prep ----
    tpose<<<nb(256 * 256), 256>>>(Wa, p_Wa1T, 256, 256, 768, 0, 256, 0);
    tpose4<<<nb(1024 * 256), 256>>>(e1f_Whh, p_WhhT4 + 0 * 262144, 1024, 256);
    tpose4<<<nb(1024 * 256), 256>>>(e1b_Whh, p_WhhT4 + 1 * 262144, 1024, 256);
    tpose4<<<nb(1024 * 256), 256>>>(e2f_Whh, p_WhhT4 + 2 * 262144, 1024, 256);
    tpose4<<<nb(1024 * 256), 256>>>(e2b_Whh, p_WhhT4 + 3 * 262144, 1024, 256);
    tpose4<<<nb(1024 * 640), 256>>>(dWih, p_dWT4, 1024, 640);
    biascat<<<4, 256>>>(e1f_b, e1b_b, p_b1c);
    biascat<<<4, 256>>>(e2f_b, e2b_b, p_b2c);
    // bf16 weight splits (B operands, [N,K] row-major = raw layout, no transpose)
    splitbf16<<<nb(1024 * 128), 256>>>(e1f_Wih, p_B1hi, p_B1lo, 1024, 128, 128, 0, 1024, 0);
    splitbf16<<<nb(1024 * 128), 256>>>(e1b_Wih, p_B1hi, p_B1lo, 1024, 128, 128, 0, 1024, 1024);
    splitbf16<<<nb(1024 * 512), 256>>>(e2f_Wih, p_B2hi, p_B2lo, 1024, 512, 512, 0, 1024, 0);
    splitbf16<<<nb(1024 * 512), 256>>>(e2b_Wih, p_B2hi, p_B2lo, 1024, 512, 512, 0, 1024, 1024);
    splitbf16<<<nb(256 * 512), 256>>>(Wa, p_BWahi, p_BWalo, 256, 512, 768, 256, 256, 0);
    splitbf16<<<nb(VPAD * 768), 256>>>(Wfc, p_Bfchi, p_Bfclo, Vsz, 768, 768, 0, VPAD, 0);

    // ---- encoder ----
    embed_gather<<<Bsz * Ssz, Esz>>>(src, enc_emb, p_emb);
    splitbf16<<<nb(8192 * 128), 256>>>(p_emb, p_Ahi, p_Alo, 8192, 128, 128, 0, 8192, 0);
    gemm_tc<<<dim3(64, 16), 256, TCSM>>>(p_Ahi, p_Alo, p_B1hi, p_B1lo, p_b1c, p_xW,
                                         8192, 2048, 128, 0);
    zeroK<<<nb(2 * Bsz * Hsz), 256>>>(p_h0, 2 * Bsz * Hsz);
    zeroK<<<nb(2 * Bsz * Hsz), 256>>>(p_c, 2 * Bsz * Hsz);
    for (int t = 0; t < Ssz; t++) {
        float* hp = (t & 1) ? p_h1 : p_h0;
        float* hn = (t & 1) ? p_h0 : p_h1;
        lstm_step<<<dim3(4, 16, 2), 256>>>(p_xW, p_WhhT4, hp, hn, p_c, p_out1, t);
    }
    splitbf16<<<nb(8192 * 512), 256>>>(p_out1, p_Ahi, p_Alo, 8192, 512, 512, 0, 8192, 0);
    gemm_tc<<<dim3(64, 16), 256, TCSM>>>(p_Ahi, p_Alo, p_B2hi, p_B2lo, p_b2c, p_xW,
                                         8192, 2048, 512, 0);
    zeroK<<<nb(2 * Bsz * Hsz), 256>>>(p_h0, 2 * Bsz * Hsz);
    zeroK<<<nb(2 * Bsz * Hsz), 256>>>(p_c, 2 * Bsz * Hsz);
    for (int t = 0; t < Ssz; t++) {
        float* hp = (t & 1) ? p_h1 : p_h0;
        float* hn = (t & 1) ? p_h0 : p_h1;
        lstm_step<<<dim3(4, 16, 2), 256>>>(p_xW, p_WhhT4 + 2 * 262144, hp, hn, p_c, p_enc, t);
    }

    // ---- attention precompute + decoder ----
    splitbf16<<<nb(8192 * 512), 256>>>(p_enc, p_Ahi, p_Alo, 8192, 512, 512, 0, 8192, 0);
    gemm_tc<<<dim3(64, 2), 256, TCSM>>>(p_Ahi, p_Alo, p_BWahi, p_BWalo, nullptr, p_encWa,
                                        8192, 256, 512, 0);
    dec_init<<<Bsz, Hsz>>>(p_enc, trg, p_hid, p_tok);
    for (int st = 0; st < Tsz - 1; st++) {
        dec_pre<<<Bsz, Hsz>>>(p_hid, p_Wa1T, ba, p_hWa, p_tok, dec_emb, p_xin);
        attention<<<Bsz, 256>>>(p_hWa, p_encWa, p_enc, vvec, p_xin, p_hc, st);
        dec_gates<<<dim3(4, 16), 256>>>(p_xin, p_dWT4, db, p_hid, p_hc, st);
        if (st < Tsz - 2) {
            next_tok<<<Bsz, 256>>>(trg, tfmask, st + 1,
                                   p_hc + (size_t)st * Bsz * 768, Wfc, bfc, p_tok);
        }
    }

    // ---- final projection on tensor cores: [h,context] @ Wfc.T + bfc ----
    splitbf16<<<nb(4096 * 768), 256>>>(p_hc, p_Ahi, p_Alo, 4032, 768, 768, 0, 4096, 0);
    gemm_tc<<<dim3(32, 79), 256, TCSM>>>(p_Ahi, p_Alo, p_Bfchi, p_Bfclo, bfc, out,
                                         4032, Vsz, 768, 1);
    zero_t0<<<dim3(Bsz, (Vsz + 255) / 256), 256>>>(out);
}